// round 4
// baseline (speedup 1.0000x reference)
#include <cuda_runtime.h>
#include <cstddef>

// out[t, e] = cos(t) * rowsum(W[e,:]) + b[e]
// T = 65536, E = 1024. Pure store-bound: 256 MB of fp32 output.
// x (d_in with 2M+ elements) is mathematically unused and never read.

#define EDIM      1024
#define THREADS   256          // one float4 (4 e-values) per thread per row
#define ROWS      32           // t-rows per block

__global__ __launch_bounds__(THREADS, 8)
void pe_quantum_kernel(const float* __restrict__ W,   // [E, 8]
                       const float* __restrict__ b,   // [E]
                       float4* __restrict__ out,      // [T, E/4] as float4
                       int T)
{
    const int i = threadIdx.x;             // 0..255 -> e block [4i, 4i+4)
    const int t0 = blockIdx.x * ROWS;

    // --- per-thread constants: a_k = sum_q W[4i+k, q], held in registers ---
    // Thread i reads W floats [128*i/4 .. ) : 32 contiguous floats = 8 float4,
    // contiguous across threads too (fully coalesced; W is 8 KB, L1/L2 hot).
    const float4* W4 = reinterpret_cast<const float4*>(W) + (size_t)i * 8;
    float a0, a1, a2, a3;
    {
        float4 w0 = W4[0], w1 = W4[1];     // row e=4i   (8 floats)
        float4 w2 = W4[2], w3 = W4[3];     // row e=4i+1
        float4 w4 = W4[4], w5 = W4[5];     // row e=4i+2
        float4 w6 = W4[6], w7 = W4[7];     // row e=4i+3
        a0 = (w0.x + w0.y) + (w0.z + w0.w) + (w1.x + w1.y) + (w1.z + w1.w);
        a1 = (w2.x + w2.y) + (w2.z + w2.w) + (w3.x + w3.y) + (w3.z + w3.w);
        a2 = (w4.x + w4.y) + (w4.z + w4.w) + (w5.x + w5.y) + (w5.z + w5.w);
        a3 = (w6.x + w6.y) + (w6.z + w6.w) + (w7.x + w7.y) + (w7.z + w7.w);
    }
    const float4 bb = reinterpret_cast<const float4*>(b)[i];

    // --- cos(t) once per row, shared across the block ---
    __shared__ float cost[ROWS];
    if (i < ROWS) {
        int t = t0 + i;
        cost[i] = (t < T) ? cosf((float)t) : 0.0f;   // accurate range reduction
    }
    __syncthreads();

    // --- emit ROWS coalesced STG.128 per thread ---
    #pragma unroll
    for (int r = 0; r < ROWS; ++r) {
        int t = t0 + r;
        if (t >= T) break;
        const float c = cost[r];
        float4 v;
        v.x = fmaf(c, a0, bb.x);
        v.y = fmaf(c, a1, bb.y);
        v.z = fmaf(c, a2, bb.z);
        v.w = fmaf(c, a3, bb.w);
        out[(size_t)t * (EDIM / 4) + i] = v;
    }
}

extern "C" void kernel_launch(void* const* d_in, const int* in_sizes, int n_in,
                              void* d_out, int out_size)
{
    // Identify W (E*8 = 8192 elems) and b (E = 1024 elems) by size; x is unused.
    const float* W = nullptr;
    const float* b = nullptr;
    for (int k = 0; k < n_in; ++k) {
        if (in_sizes[k] == EDIM * 8)      W = (const float*)d_in[k];
        else if (in_sizes[k] == EDIM)     b = (const float*)d_in[k];
    }
    // Fallback to metadata order (x, W, b) if sizes ever collide.
    if (!W && n_in >= 2) W = (const float*)d_in[1];
    if (!b && n_in >= 3) b = (const float*)d_in[2];

    const int T = out_size / EDIM;                 // 65536
    const int grid = (T + ROWS - 1) / ROWS;        // 2048 blocks

    pe_quantum_kernel<<<grid, THREADS>>>(W, b, (float4*)d_out, T);
}